// round 5
// baseline (speedup 1.0000x reference)
#include <cuda_runtime.h>

// SelfAttentionIEU: per-(b,h)-row attention along W.
// x:[B,C,H,W] fp32, Wq/Wk/Wv:[256,20], bq/bk/bv:[20], Wp:[20,256], bp:[256]
// out:[B,C,H,W] fp32

#define NB   16
#define NC   256
#define NH   128
#define NW   128
#define ND   20
#define NOUT 64     // fused QKV width padded from 60
#define CHUNK 16
#define NTH  256
#define QS   68     // qkv smem row stride (floats) — avoids bank conflicts
#define LS   129    // logits smem row stride
#define CS   24     // ctx smem row stride

struct SmemA {
    float W[NC][NOUT];        // fused [Wq|Wk|Wv|0] : 64 KB
    float xc[2][CHUNK][NW];   // double-buffered x chunk : 16 KB
};
struct SmemB {
    float logits[NW][LS];     // 66048 B
    float Wp[ND][NC];         // 20480 B
    float ctx[NW][CS];        // 12288 B
    float bp[NC];             // 1024 B
};
struct Smem {
    float qkv[NW][QS];        // 34816 B (outside union: live across phases)
    union { SmemA a; SmemB b; } u;
};

__global__ void __launch_bounds__(NTH, 1)
attn_kernel(const float* __restrict__ x,
            const float* __restrict__ gWq, const float* __restrict__ gbq,
            const float* __restrict__ gWk, const float* __restrict__ gbk,
            const float* __restrict__ gWv, const float* __restrict__ gbv,
            const float* __restrict__ gWp, const float* __restrict__ gbp,
            float* __restrict__ out)
{
    extern __shared__ char smraw[];
    Smem& s = *reinterpret_cast<Smem*>(smraw);
    const int t  = threadIdx.x;
    const int bh = blockIdx.x;
    const int b  = bh >> 7;    // H = 128
    const int h  = bh & 127;
    const int HW = NH * NW;
    const float* xbase = x   + (b * NC) * HW + h * NW;
    float*       obase = out + (b * NC) * HW + h * NW;

    // ---------------- Phase A: QKV = x_row @ [Wq|Wk|Wv] + bias ----------------
    // Load fused weight [256][64] into smem (cols 60..63 zero).
    for (int i = t; i < NC * NOUT; i += NTH) {
        int c = i >> 6, j = i & 63;
        float v;
        if      (j < 20) v = gWq[c * 20 + j];
        else if (j < 40) v = gWk[c * 20 + (j - 20)];
        else if (j < 60) v = gWv[c * 20 + (j - 40)];
        else             v = 0.f;
        s.u.a.W[c][j] = v;
    }

    const int tx = t & 31;   // token group: w = tx*4 + i
    const int ty = t >> 5;   // output group: j = ty*8 + jj

    float acc[4][8];
    #pragma unroll
    for (int jj = 0; jj < 8; jj++) {
        int j = ty * 8 + jj;
        float bias;
        if      (j < 20) bias = gbq[j];
        else if (j < 40) bias = gbk[j - 20];
        else if (j < 60) bias = gbv[j - 40];
        else             bias = 0.f;
        #pragma unroll
        for (int i = 0; i < 4; i++) acc[i][jj] = bias;
    }

    // Stage chunk 0
    #pragma unroll
    for (int k = 0; k < 8; k++) {
        int idx = t + k * NTH;                       // [0, 2048)
        s.u.a.xc[0][idx >> 7][idx & 127] = xbase[(idx >> 7) * HW + (idx & 127)];
    }
    __syncthreads();

    float r[8];
    #pragma unroll 1
    for (int ch = 0; ch < NC / CHUNK; ch++) {
        // Prefetch next chunk to registers (overlaps with compute below)
        if (ch + 1 < NC / CHUNK) {
            int c0n = (ch + 1) * CHUNK;
            #pragma unroll
            for (int k = 0; k < 8; k++) {
                int idx = t + k * NTH;
                r[k] = xbase[(c0n + (idx >> 7)) * HW + (idx & 127)];
            }
        }
        const int c0 = ch * CHUNK, buf = ch & 1;
        #pragma unroll
        for (int cc = 0; cc < CHUNK; cc++) {
            float4 xv = *reinterpret_cast<const float4*>(&s.u.a.xc[buf][cc][tx * 4]);
            float4 w0 = *reinterpret_cast<const float4*>(&s.u.a.W[c0 + cc][ty * 8]);
            float4 w1 = *reinterpret_cast<const float4*>(&s.u.a.W[c0 + cc][ty * 8 + 4]);
            float xr[4] = {xv.x, xv.y, xv.z, xv.w};
            float wr[8] = {w0.x, w0.y, w0.z, w0.w, w1.x, w1.y, w1.z, w1.w};
            #pragma unroll
            for (int i = 0; i < 4; i++)
                #pragma unroll
                for (int jj = 0; jj < 8; jj++)
                    acc[i][jj] += xr[i] * wr[jj];
        }
        __syncthreads();
        if (ch + 1 < NC / CHUNK) {
            #pragma unroll
            for (int k = 0; k < 8; k++) {
                int idx = t + k * NTH;
                s.u.a.xc[buf ^ 1][idx >> 7][idx & 127] = r[k];
            }
            __syncthreads();
        }
    }

    // Write QKV [w][0..59] to smem (cols 60..63 are zeros — harmless)
    #pragma unroll
    for (int i = 0; i < 4; i++) {
        int w = tx * 4 + i;
        *reinterpret_cast<float4*>(&s.qkv[w][ty * 8]) =
            make_float4(acc[i][0], acc[i][1], acc[i][2], acc[i][3]);
        *reinterpret_cast<float4*>(&s.qkv[w][ty * 8 + 4]) =
            make_float4(acc[i][4], acc[i][5], acc[i][6], acc[i][7]);
    }
    __syncthreads();

    // ---------------- Phase B: attention + projection ----------------
    // Cooperative load of Wp / bp (into union region; safe after sync above)
    for (int i = t; i < ND * NC; i += NTH) (&s.u.b.Wp[0][0])[i] = gWp[i];
    for (int i = t; i < NC; i += NTH)      s.u.b.bp[i] = gbp[i];

    // logits: 2 threads per query row
    const int q  = t >> 1;
    const int hb = t & 1;
    float Qr[20];
    #pragma unroll
    for (int d4 = 0; d4 < 5; d4++) {
        float4 v = *reinterpret_cast<const float4*>(&s.qkv[q][d4 * 4]);
        Qr[d4*4+0] = v.x; Qr[d4*4+1] = v.y; Qr[d4*4+2] = v.z; Qr[d4*4+3] = v.w;
    }
    float mx = -3.0e38f;
    #pragma unroll 4
    for (int jj = 0; jj < 64; jj++) {
        int j = hb * 64 + jj;
        float dot = 0.f;
        #pragma unroll
        for (int d4 = 0; d4 < 5; d4++) {
            float4 kv = *reinterpret_cast<const float4*>(&s.qkv[j][20 + d4 * 4]);
            dot += Qr[d4*4+0]*kv.x + Qr[d4*4+1]*kv.y + Qr[d4*4+2]*kv.z + Qr[d4*4+3]*kv.w;
        }
        s.u.b.logits[q][j] = dot;
        mx = fmaxf(mx, dot);
    }
    mx = fmaxf(mx, __shfl_xor_sync(0xffffffffu, mx, 1));

    float ssum = 0.f;
    #pragma unroll 4
    for (int jj = 0; jj < 64; jj++) {
        int j = hb * 64 + jj;
        float e = __expf(s.u.b.logits[q][j] - mx);
        s.u.b.logits[q][j] = e;
        ssum += e;
    }
    ssum += __shfl_xor_sync(0xffffffffu, ssum, 1);
    __syncwarp();   // partner's exp-values + our reads of its half

    // ctx = P @ V  (V = qkv cols 40..59); thread owns 10 of 20 dims
    float cacc[10];
    #pragma unroll
    for (int k2 = 0; k2 < 10; k2++) cacc[k2] = 0.f;
    const int vo = 40 + hb * 10;
    #pragma unroll 2
    for (int j = 0; j < NW; j++) {
        float p = s.u.b.logits[q][j];
        #pragma unroll
        for (int k2 = 0; k2 < 5; k2++) {
            float2 vv = *reinterpret_cast<const float2*>(&s.qkv[j][vo + k2 * 2]);
            cacc[k2*2+0] += p * vv.x;
            cacc[k2*2+1] += p * vv.y;
        }
    }
    const float inv = 1.0f / ssum;
    #pragma unroll
    for (int k2 = 0; k2 < 10; k2++)
        s.u.b.ctx[q][hb * 10 + k2] = cacc[k2] * inv;
    __syncthreads();

    // out[:, w] = ctx[w] @ Wp + bp ; thread = (w, half of channels)
    const int w     = t & 127;
    const int chalf = t >> 7;
    float ctxr[20];
    #pragma unroll
    for (int d4 = 0; d4 < 5; d4++) {
        float4 v = *reinterpret_cast<const float4*>(&s.u.b.ctx[w][d4 * 4]);
        ctxr[d4*4+0] = v.x; ctxr[d4*4+1] = v.y; ctxr[d4*4+2] = v.z; ctxr[d4*4+3] = v.w;
    }
    #pragma unroll 1
    for (int c4 = 0; c4 < 32; c4++) {
        int c = chalf * 128 + c4 * 4;
        float4 oacc = *reinterpret_cast<const float4*>(&s.u.b.bp[c]);
        #pragma unroll
        for (int d = 0; d < 20; d++) {
            float4 wv = *reinterpret_cast<const float4*>(&s.u.b.Wp[d][c]);
            oacc.x += ctxr[d] * wv.x;
            oacc.y += ctxr[d] * wv.y;
            oacc.z += ctxr[d] * wv.z;
            oacc.w += ctxr[d] * wv.w;
        }
        obase[(c + 0) * HW + w] = oacc.x;   // coalesced across warp (w contiguous)
        obase[(c + 1) * HW + w] = oacc.y;
        obase[(c + 2) * HW + w] = oacc.z;
        obase[(c + 3) * HW + w] = oacc.w;
    }
}

extern "C" void kernel_launch(void* const* d_in, const int* in_sizes, int n_in,
                              void* d_out, int out_size)
{
    (void)in_sizes; (void)n_in; (void)out_size;
    const float* x  = (const float*)d_in[0];
    const float* Wq = (const float*)d_in[1];
    const float* bq = (const float*)d_in[2];
    const float* Wk = (const float*)d_in[3];
    const float* bk = (const float*)d_in[4];
    const float* Wv = (const float*)d_in[5];
    const float* bv = (const float*)d_in[6];
    const float* Wp = (const float*)d_in[7];
    const float* bp = (const float*)d_in[8];
    float* out = (float*)d_out;

    const int smem = (int)sizeof(Smem);
    cudaFuncSetAttribute(attn_kernel, cudaFuncAttributeMaxDynamicSharedMemorySize, smem);
    attn_kernel<<<NB * NH, NTH, smem>>>(x, Wq, bq, Wk, bk, Wv, bv, Wp, bp, out);
}

// round 6
// speedup vs baseline: 1.3880x; 1.3880x over previous
#include <cuda_runtime.h>

// SelfAttentionIEU: per-(b,h)-row attention along W axis.
// x:[16,256,128,128] fp32 -> out same shape.
// Round-2 design: 512 thr, 2 CTAs/SM (106 KB smem), online softmax (no logits
// smem), f32x2 packed FMA, staggered K/V rows to avoid bank conflicts.

#define NB   16
#define NC   256
#define NH   128
#define NW   128
#define ND   20
#define NOUT 64
#define CHUNK 8
#define NTH  512
#define QS   68     // qkv smem row stride (floats); 272 B = 17*16 (float4-safe)
#define CS   20     // ctx smem row stride (80 B, 16-aligned)

typedef unsigned long long u64;

__device__ __forceinline__ u64 pack2(float lo, float hi) {
    u64 r; asm("mov.b64 %0, {%1, %2};" : "=l"(r) : "f"(lo), "f"(hi)); return r;
}
__device__ __forceinline__ u64 dup2(float v) { return pack2(v, v); }
__device__ __forceinline__ void unpack2(u64 p, float& lo, float& hi) {
    asm("mov.b64 {%0, %1}, %2;" : "=f"(lo), "=f"(hi) : "l"(p));
}
__device__ __forceinline__ u64 fma2(u64 a, u64 b, u64 c) {
    u64 d; asm("fma.rn.f32x2 %0, %1, %2, %3;" : "=l"(d) : "l"(a), "l"(b), "l"(c)); return d;
}
__device__ __forceinline__ u64 mul2(u64 a, u64 b) {
    u64 d; asm("mul.rn.f32x2 %0, %1, %2;" : "=l"(d) : "l"(a), "l"(b)); return d;
}
__device__ __forceinline__ u64 d2u(double x) { return __double_as_longlong(x); }

struct SmemA {
    float W[NC][NOUT];        // fused [Wq|Wk|Wv|0] : 65536 B
    float xc[2][CHUNK][NW];   // double-buffered x chunk : 8192 B
};
struct SmemB {
    float Wp[ND][NC];         // 20480 B
    float ctx[NW][CS];        // 10240 B
    float bp[NC];             // 1024 B
};
struct Smem {
    float qkv[NW][QS];        // 34816 B, live across phases
    union { SmemA a; SmemB b; } u;
};  // total 108544 B -> 2 CTAs/SM

__global__ void __launch_bounds__(NTH, 2)
attn_kernel(const float* __restrict__ x,
            const float* __restrict__ gWq, const float* __restrict__ gbq,
            const float* __restrict__ gWk, const float* __restrict__ gbk,
            const float* __restrict__ gWv, const float* __restrict__ gbv,
            const float* __restrict__ gWp, const float* __restrict__ gbp,
            float* __restrict__ out)
{
    extern __shared__ char smraw[];
    Smem& s = *reinterpret_cast<Smem*>(smraw);
    const int t  = threadIdx.x;
    const int bh = blockIdx.x;
    const int b  = bh >> 7;
    const int h  = bh & 127;
    const int HW = NH * NW;
    const float* xbase = x   + (b * NC) * HW + h * NW;
    float*       obase = out + (b * NC) * HW + h * NW;

    // ---------------- Phase A: QKV = x_row @ [Wq|Wk|Wv] + bias ----------------
    for (int i = t; i < NC * NOUT; i += NTH) {
        int c = i >> 6, j = i & 63;
        float v;
        if      (j < 20) v = gWq[c * 20 + j];
        else if (j < 40) v = gWk[c * 20 + (j - 20)];
        else if (j < 60) v = gWv[c * 20 + (j - 40)];
        else             v = 0.f;
        s.u.a.W[c][j] = v;
    }

    const int tx = t & 63;   // token group: w = tx*2 + i
    const int ty = t >> 6;   // output group: j = ty*8 + 2*jj2

    // accumulators: 2 tokens x 4 output-pairs, f32x2 packed over output pairs
    u64 accp[2][4];
    #pragma unroll
    for (int jj2 = 0; jj2 < 4; jj2++) {
        int j = ty * 8 + jj2 * 2;
        float b0, b1;
        if      (j < 20) { b0 = gbq[j];      b1 = gbq[j + 1 - 0]; }
        else if (j < 40) { b0 = gbk[j - 20]; b1 = gbk[j - 19]; }
        else if (j < 60) { b0 = gbv[j - 40]; b1 = gbv[j - 39]; }
        else             { b0 = 0.f;         b1 = 0.f; }
        u64 bp2 = pack2(b0, b1);
        accp[0][jj2] = bp2; accp[1][jj2] = bp2;
    }

    // stage chunk 0 (CHUNK*NW = 1024 elems, 2 per thread)
    #pragma unroll
    for (int k = 0; k < 2; k++) {
        int idx = t + k * NTH;
        s.u.a.xc[0][idx >> 7][idx & 127] = xbase[(idx >> 7) * HW + (idx & 127)];
    }
    __syncthreads();

    float r[2];
    #pragma unroll 1
    for (int ch = 0; ch < NC / CHUNK; ch++) {
        if (ch + 1 < NC / CHUNK) {
            int c0n = (ch + 1) * CHUNK;
            #pragma unroll
            for (int k = 0; k < 2; k++) {
                int idx = t + k * NTH;
                r[k] = xbase[(c0n + (idx >> 7)) * HW + (idx & 127)];
            }
        }
        const int c0 = ch * CHUNK, buf = ch & 1;
        #pragma unroll
        for (int cc = 0; cc < CHUNK; cc++) {
            float2 xv = *reinterpret_cast<const float2*>(&s.u.a.xc[buf][cc][tx * 2]);
            const double2* wrow = reinterpret_cast<const double2*>(&s.u.a.W[c0 + cc][ty * 8]);
            double2 wA = wrow[0], wB = wrow[1];   // 4 ready-made f32x2 output pairs
            u64 wp0 = d2u(wA.x), wp1 = d2u(wA.y), wp2 = d2u(wB.x), wp3 = d2u(wB.y);
            u64 xa0 = dup2(xv.x), xa1 = dup2(xv.y);
            accp[0][0] = fma2(xa0, wp0, accp[0][0]);
            accp[0][1] = fma2(xa0, wp1, accp[0][1]);
            accp[0][2] = fma2(xa0, wp2, accp[0][2]);
            accp[0][3] = fma2(xa0, wp3, accp[0][3]);
            accp[1][0] = fma2(xa1, wp0, accp[1][0]);
            accp[1][1] = fma2(xa1, wp1, accp[1][1]);
            accp[1][2] = fma2(xa1, wp2, accp[1][2]);
            accp[1][3] = fma2(xa1, wp3, accp[1][3]);
        }
        __syncthreads();
        if (ch + 1 < NC / CHUNK) {
            #pragma unroll
            for (int k = 0; k < 2; k++) {
                int idx = t + k * NTH;
                s.u.a.xc[buf ^ 1][idx >> 7][idx & 127] = r[k];
            }
            __syncthreads();
        }
    }

    // writeback QKV rows (cols 60..63 zeros, harmless)
    #pragma unroll
    for (int i = 0; i < 2; i++) {
        int w = tx * 2 + i;
        float f0,f1,f2,f3,f4,f5,f6,f7;
        unpack2(accp[i][0], f0, f1);
        unpack2(accp[i][1], f2, f3);
        unpack2(accp[i][2], f4, f5);
        unpack2(accp[i][3], f6, f7);
        *reinterpret_cast<float4*>(&s.qkv[w][ty * 8])     = make_float4(f0, f1, f2, f3);
        *reinterpret_cast<float4*>(&s.qkv[w][ty * 8 + 4]) = make_float4(f4, f5, f6, f7);
    }
    __syncthreads();

    // ---------------- Phase B: fused online-softmax attention ----------------
    // cooperative Wp/bp load (overlaps dead W region; read only after barrier)
    for (int i = t; i < ND * NC; i += NTH) (&s.u.b.Wp[0][0])[i] = gWp[i];
    for (int i = t; i < NC; i += NTH)      s.u.b.bp[i] = gbp[i];

    const int q  = t >> 2;   // 128 queries, 4 threads each
    const int hb = t & 3;    // each owns 32 keys

    // Q packed into 10 f32x2 (dim pairs)
    u64 Qp[10];
    {
        const double2* qrow = reinterpret_cast<const double2*>(&s.qkv[q][0]);
        #pragma unroll
        for (int k = 0; k < 5; k++) {
            double2 qq = qrow[k];
            Qp[2 * k]     = d2u(qq.x);
            Qp[2 * k + 1] = d2u(qq.y);
        }
    }

    u64 ctxp[10];
    #pragma unroll
    for (int k = 0; k < 10; k++) ctxp[k] = 0ULL;   // (0.f,0.f)
    float mx   = -3.0e38f;
    float ssum = 0.f;

    #pragma unroll 2
    for (int jj = 0; jj < 32; jj++) {
        // stagger start per hb: 4 rows in flight land on distinct bank groups
        int j = (hb << 5) | ((jj + hb) & 31);
        const double2* krow = reinterpret_cast<const double2*>(&s.qkv[j][20]);
        u64 dp = 0ULL;
        #pragma unroll
        for (int k = 0; k < 5; k++) {
            double2 kk = krow[k];
            dp = fma2(Qp[2 * k],     d2u(kk.x), dp);
            dp = fma2(Qp[2 * k + 1], d2u(kk.y), dp);
        }
        float dlo, dhi; unpack2(dp, dlo, dhi);
        float d = dlo + dhi;

        if (d > mx) {                       // rescale running state
            float alpha = __expf(mx - d);   // first iter: exp(-inf)=0, state is 0
            ssum *= alpha;
            u64 a2 = dup2(alpha);
            #pragma unroll
            for (int k = 0; k < 10; k++) ctxp[k] = mul2(ctxp[k], a2);
            mx = d;
        }
        float p = __expf(d - mx);
        ssum += p;
        u64 p2 = dup2(p);
        const double2* vrow = reinterpret_cast<const double2*>(&s.qkv[j][40]);
        #pragma unroll
        for (int k = 0; k < 5; k++) {
            double2 vv = vrow[k];
            ctxp[2 * k]     = fma2(p2, d2u(vv.x), ctxp[2 * k]);
            ctxp[2 * k + 1] = fma2(p2, d2u(vv.y), ctxp[2 * k + 1]);
        }
    }

    // merge 4 partials (lanes differing in bits 0..1) via shfl
    float ctxf[20];
    #pragma unroll
    for (int k = 0; k < 10; k++) unpack2(ctxp[k], ctxf[2 * k], ctxf[2 * k + 1]);
    #pragma unroll
    for (int st = 1; st <= 2; st <<= 1) {
        float m2 = __shfl_xor_sync(0xffffffffu, mx,   st);
        float s2 = __shfl_xor_sync(0xffffffffu, ssum, st);
        float mn = fmaxf(mx, m2);
        float a  = __expf(mx - mn);
        float bb = __expf(m2 - mn);
        ssum = a * ssum + bb * s2;
        #pragma unroll
        for (int k = 0; k < 20; k++) {
            float c2 = __shfl_xor_sync(0xffffffffu, ctxf[k], st);
            ctxf[k] = a * ctxf[k] + bb * c2;
        }
        mx = mn;
    }
    if (hb == 0) {
        float inv = 1.0f / ssum;
        #pragma unroll
        for (int k = 0; k < 20; k++) s.u.b.ctx[q][k] = ctxf[k] * inv;
    }
    __syncthreads();

    // ---------------- Projection: out[:,w] = ctx[w] @ Wp + bp ----------------
    const int w  = t & 127;
    const int cq = t >> 7;   // quarter of channels
    float ctxr[20];
    {
        const float4* crow = reinterpret_cast<const float4*>(&s.u.b.ctx[w][0]);
        #pragma unroll
        for (int k = 0; k < 5; k++) {
            float4 v = crow[k];
            ctxr[4*k+0] = v.x; ctxr[4*k+1] = v.y; ctxr[4*k+2] = v.z; ctxr[4*k+3] = v.w;
        }
    }
    #pragma unroll 1
    for (int c4 = 0; c4 < 16; c4++) {
        int c = cq * 64 + c4 * 4;
        float4 bb = *reinterpret_cast<const float4*>(&s.u.b.bp[c]);
        u64 o0 = pack2(bb.x, bb.y);
        u64 o1 = pack2(bb.z, bb.w);
        #pragma unroll
        for (int d = 0; d < 20; d++) {
            const double2* wp = reinterpret_cast<const double2*>(&s.u.b.Wp[d][c]);
            double2 ww = *wp;
            u64 cd = dup2(ctxr[d]);
            o0 = fma2(cd, d2u(ww.x), o0);
            o1 = fma2(cd, d2u(ww.y), o1);
        }
        float e0,e1,e2,e3;
        unpack2(o0, e0, e1);
        unpack2(o1, e2, e3);
        obase[(c + 0) * HW + w] = e0;
        obase[(c + 1) * HW + w] = e1;
        obase[(c + 2) * HW + w] = e2;
        obase[(c + 3) * HW + w] = e3;
    }
}

extern "C" void kernel_launch(void* const* d_in, const int* in_sizes, int n_in,
                              void* d_out, int out_size)
{
    (void)in_sizes; (void)n_in; (void)out_size;
    const float* x  = (const float*)d_in[0];
    const float* Wq = (const float*)d_in[1];
    const float* bq = (const float*)d_in[2];
    const float* Wk = (const float*)d_in[3];
    const float* bk = (const float*)d_in[4];
    const float* Wv = (const float*)d_in[5];
    const float* bv = (const float*)d_in[6];
    const float* Wp = (const float*)d_in[7];
    const float* bp = (const float*)d_in[8];
    float* out = (float*)d_out;

    const int smem = (int)sizeof(Smem);
    cudaFuncSetAttribute(attn_kernel, cudaFuncAttributeMaxDynamicSharedMemorySize, smem);
    attn_kernel<<<NB * NH, NTH, smem>>>(x, Wq, bq, Wk, bk, Wv, bv, Wp, bp, out);
}